// round 2
// baseline (speedup 1.0000x reference)
#include <cuda_runtime.h>
#include <math.h>

#define BATCH   16
#define LSEQ    2048
#define DMODEL  256
#define DINNER  512
#define DSTATE  16
#define NOUT    256
#define NROWS   (BATCH*LSEQ)   /* 32768 */

// ---------------- device scratch (no allocations allowed) ----------------
__device__ float  g_xz[(size_t)NROWS * 1024];        // in_proj output (x | silu(z))
__device__ float4 g_scanin[(size_t)NROWS * DINNER];  // (delta, delta*xc, silu(z), xc*D)
__device__ float2 g_bc[(size_t)NROWS * DSTATE];      // (B_n, C_n) interleaved
__device__ float  g_y[(size_t)NROWS * DINNER];       // scan output (pre out_proj)
__device__ float  g_t1[(size_t)NROWS * NOUT];        // silu(out_proj)
__device__ float  g_psum[512 * 2];                   // per-block (sum, sumsq)
__device__ float2 g_stats[BATCH];                    // (mean, rstd)

__device__ __forceinline__ float silu_f(float v) {
    return v / (1.f + __expf(-v));
}

// ---------------- NT SGEMM: C[M,N] = A[M,K] * B[N,K]^T --------------------
// 128x128 tile, BK=8, 256 threads, 8x8/thread, double-buffered smem with
// register prefetch (1 sync per k-tile).
// EPI: 0 = plain, 1 = silu, 2 = +bias + per-block (sum,sumsq)->g_psum,
//      3 = silu only on column-blocks bn>=4 (the z half of in_proj output)
template <int EPI>
__global__ void __launch_bounds__(256, 2)
gemm_nt_kernel(const float* __restrict__ A, const float* __restrict__ B,
               float* __restrict__ C, int M, int N, int K,
               const float* __restrict__ bias)
{
    __shared__ float As[2][8][132];
    __shared__ float Bs[2][8][132];
    __shared__ float rs[256];
    __shared__ float rss[256];

    const int tid = threadIdx.x;
    const int bm = blockIdx.y, bn = blockIdx.x;

    const int lrow = tid >> 1;          // 0..127
    const int lcol = (tid & 1) * 4;     // 0 or 4
    const float* Ag = A + (size_t)(bm * 128 + lrow) * K + lcol;
    const float* Bg = B + (size_t)(bn * 128 + lrow) * K + lcol;

    const int tm = (tid >> 4) * 8;
    const int tn = (tid & 15) * 8;

    float c[8][8] = {};

    const int nk = K / 8;

    // prefetch tile 0
    float4 av = *(const float4*)(Ag);
    float4 bv = *(const float4*)(Bg);
    As[0][lcol + 0][lrow] = av.x; As[0][lcol + 1][lrow] = av.y;
    As[0][lcol + 2][lrow] = av.z; As[0][lcol + 3][lrow] = av.w;
    Bs[0][lcol + 0][lrow] = bv.x; Bs[0][lcol + 1][lrow] = bv.y;
    Bs[0][lcol + 2][lrow] = bv.z; Bs[0][lcol + 3][lrow] = bv.w;
    __syncthreads();

    for (int kt = 0; kt < nk; ++kt) {
        const int buf = kt & 1;
        const bool more = (kt + 1 < nk);
        if (more) {
            av = *(const float4*)(Ag + (kt + 1) * 8);
            bv = *(const float4*)(Bg + (kt + 1) * 8);
        }
#pragma unroll
        for (int k = 0; k < 8; ++k) {
            float4 a0 = *(const float4*)&As[buf][k][tm];
            float4 a1 = *(const float4*)&As[buf][k][tm + 4];
            float4 b0 = *(const float4*)&Bs[buf][k][tn];
            float4 b1 = *(const float4*)&Bs[buf][k][tn + 4];
            float a[8] = {a0.x,a0.y,a0.z,a0.w,a1.x,a1.y,a1.z,a1.w};
            float b[8] = {b0.x,b0.y,b0.z,b0.w,b1.x,b1.y,b1.z,b1.w};
#pragma unroll
            for (int i = 0; i < 8; ++i)
#pragma unroll
                for (int j = 0; j < 8; ++j)
                    c[i][j] = fmaf(a[i], b[j], c[i][j]);
        }
        if (more) {
            const int nb = buf ^ 1;
            As[nb][lcol + 0][lrow] = av.x; As[nb][lcol + 1][lrow] = av.y;
            As[nb][lcol + 2][lrow] = av.z; As[nb][lcol + 3][lrow] = av.w;
            Bs[nb][lcol + 0][lrow] = bv.x; Bs[nb][lcol + 1][lrow] = bv.y;
            Bs[nb][lcol + 2][lrow] = bv.z; Bs[nb][lcol + 3][lrow] = bv.w;
            __syncthreads();
        }
    }

    float s = 0.f, ss = 0.f;
    const bool do_silu = (EPI == 1) || (EPI == 3 && bn >= 4);
#pragma unroll
    for (int i = 0; i < 8; ++i) {
        float* Crow = C + (size_t)(bm * 128 + tm + i) * N + bn * 128 + tn;
#pragma unroll
        for (int j = 0; j < 8; j += 4) {
            float v[4];
#pragma unroll
            for (int q = 0; q < 4; ++q) {
                float x = c[i][j + q];
                if (do_silu) x = silu_f(x);
                if (EPI == 2) {
                    x += bias[bn * 128 + tn + j + q];
                    s += x; ss += x * x;
                }
                v[q] = x;
            }
            *(float4*)(Crow + j) = make_float4(v[0], v[1], v[2], v[3]);
        }
    }

    if (EPI == 2) {
        rs[tid] = s; rss[tid] = ss;
        __syncthreads();
        for (int off = 128; off > 0; off >>= 1) {
            if (tid < off) { rs[tid] += rs[tid + off]; rss[tid] += rss[tid + off]; }
            __syncthreads();
        }
        if (tid == 0) {
            int pid = bm * gridDim.x + bn;
            g_psum[2 * pid] = rs[0];
            g_psum[2 * pid + 1] = rss[0];
        }
    }
}

// ---------- fused causal conv + SiLU + x_proj + dt_proj + pack -----------
// one block = 16 tokens x 512 channels; 512 threads (one per channel)
#define TOK 16
__global__ void __launch_bounds__(512)
convproj_kernel(const float* __restrict__ conv_w, const float* __restrict__ conv_b,
                const float* __restrict__ x_proj_w, const float* __restrict__ dt_proj_w,
                const float* __restrict__ dt_proj_b, const float* __restrict__ D_skip)
{
    const int b  = blockIdx.x >> 7;
    const int l0 = (blockIdx.x & 127) * TOK;
    const int d  = threadIdx.x;

    __shared__ float xc_s[TOK][512];
    __shared__ float xdbl_s[TOK][48];

    // ---- causal depthwise conv (D_CONV=4) with register sliding window ----
    {
        float4 cw = ((const float4*)conv_w)[d];
        float cb = conv_b[d];
        const float* xcol = g_xz + (size_t)(b * 2048 + l0) * 1024 + d;
        float w0 = (l0 >= 3 || l0 + 0 >= 3) ? 0.f : 0.f; // placeholder
        float w1, w2;
        w0 = (l0 - 3 >= 0) ? xcol[-3 * 1024] : 0.f;
        w1 = (l0 - 2 >= 0) ? xcol[-2 * 1024] : 0.f;
        w2 = (l0 - 1 >= 0) ? xcol[-1 * 1024] : 0.f;
#pragma unroll
        for (int t = 0; t < TOK; ++t) {
            float cur = xcol[t * 1024];
            float acc = cb;
            acc = fmaf(w0, cw.x, acc);
            acc = fmaf(w1, cw.y, acc);
            acc = fmaf(w2, cw.z, acc);
            acc = fmaf(cur, cw.w, acc);
            xc_s[t][d] = silu_f(acc);
            w0 = w1; w1 = w2; w2 = cur;
        }
    }
    __syncthreads();

    // ---- x_dbl[t][48] = xc[t] . x_proj_w^T : 16 warps x 3 outputs --------
    {
        const int warp = d >> 5, lane = d & 31;
        // weights for 3 rows, kept in registers as float4 slices
        float4 wv[3][4];
        const float4* xw4 = (const float4*)x_proj_w;
#pragma unroll
        for (int jj = 0; jj < 3; ++jj) {
            const float4* wrow = xw4 + (size_t)(warp * 3 + jj) * 128;
#pragma unroll
            for (int q = 0; q < 4; ++q)
                wv[jj][q] = wrow[lane + q * 32];
        }
#pragma unroll
        for (int t = 0; t < TOK; ++t) {
            float4 xv[4];
            const float4* xr = (const float4*)&xc_s[t][0];
#pragma unroll
            for (int q = 0; q < 4; ++q) xv[q] = xr[lane + q * 32];
            float a0 = 0.f, a1 = 0.f, a2 = 0.f;
#pragma unroll
            for (int q = 0; q < 4; ++q) {
                a0 = fmaf(xv[q].x, wv[0][q].x, a0); a0 = fmaf(xv[q].y, wv[0][q].y, a0);
                a0 = fmaf(xv[q].z, wv[0][q].z, a0); a0 = fmaf(xv[q].w, wv[0][q].w, a0);
                a1 = fmaf(xv[q].x, wv[1][q].x, a1); a1 = fmaf(xv[q].y, wv[1][q].y, a1);
                a1 = fmaf(xv[q].z, wv[1][q].z, a1); a1 = fmaf(xv[q].w, wv[1][q].w, a1);
                a2 = fmaf(xv[q].x, wv[2][q].x, a2); a2 = fmaf(xv[q].y, wv[2][q].y, a2);
                a2 = fmaf(xv[q].z, wv[2][q].z, a2); a2 = fmaf(xv[q].w, wv[2][q].w, a2);
            }
#pragma unroll
            for (int off = 16; off; off >>= 1) {
                a0 += __shfl_xor_sync(0xffffffffu, a0, off);
                a1 += __shfl_xor_sync(0xffffffffu, a1, off);
                a2 += __shfl_xor_sync(0xffffffffu, a2, off);
            }
            if (lane == 0) {
                xdbl_s[t][warp * 3 + 0] = a0;
                xdbl_s[t][warp * 3 + 1] = a1;
                xdbl_s[t][warp * 3 + 2] = a2;
            }
        }
    }
    __syncthreads();

    // ---- delta = softplus(dt @ dt_proj_w^T + b), pack scan inputs --------
    {
        const float4* dw = (const float4*)(dt_proj_w + d * 16);
        float4 dw0 = dw[0], dw1 = dw[1], dw2 = dw[2], dw3 = dw[3];
        const float dtb = dt_proj_b[d];
        const float Dv = D_skip[d];
        const float* zptr = g_xz + (size_t)(b * 2048 + l0) * 1024 + 512 + d;
        float4* outp = g_scanin + (size_t)(b * 2048 + l0) * 512 + d;
#pragma unroll
        for (int t = 0; t < TOK; ++t) {
            const float4* xr = (const float4*)&xdbl_s[t][0];
            float4 x0 = xr[0], x1 = xr[1], x2 = xr[2], x3 = xr[3];
            float dt = dtb;
            dt = fmaf(x0.x, dw0.x, dt); dt = fmaf(x0.y, dw0.y, dt);
            dt = fmaf(x0.z, dw0.z, dt); dt = fmaf(x0.w, dw0.w, dt);
            dt = fmaf(x1.x, dw1.x, dt); dt = fmaf(x1.y, dw1.y, dt);
            dt = fmaf(x1.z, dw1.z, dt); dt = fmaf(x1.w, dw1.w, dt);
            dt = fmaf(x2.x, dw2.x, dt); dt = fmaf(x2.y, dw2.y, dt);
            dt = fmaf(x2.z, dw2.z, dt); dt = fmaf(x2.w, dw2.w, dt);
            dt = fmaf(x3.x, dw3.x, dt); dt = fmaf(x3.y, dw3.y, dt);
            dt = fmaf(x3.z, dw3.z, dt); dt = fmaf(x3.w, dw3.w, dt);
            float delta = (dt > 20.f) ? dt : log1pf(__expf(dt));
            float xc = xc_s[t][d];
            float sz = zptr[(size_t)t * 1024];   // already silu'd by gemm<3>
            outp[(size_t)t * 512] = make_float4(delta, delta * xc, sz, xc * Dv);
        }
    }

    // ---- B, C pack: g_bc[row][n] = (B_n, C_n) ----------------------------
    if (d < TOK * DSTATE) {
        const int t = d >> 4, n = d & 15;
        g_bc[(size_t)(b * 2048 + l0 + t) * 16 + n] =
            make_float2(xdbl_s[t][16 + n], xdbl_s[t][32 + n]);
    }
}

// ---------------------- diagonal selective scan ---------------------------
// warp = 4 channels (d) x 8 lanes x 2 states/lane; 2048 warps total.
__global__ void __launch_bounds__(128)
scan_kernel(const float* __restrict__ A_log)
{
    const int w = blockIdx.x * 4 + (threadIdx.x >> 5);  // 0..2047
    const int b = w >> 7;
    const int dbase = (w & 127) * 4;
    const int lane = threadIdx.x & 31;
    const int li = lane & 7;             // lane within d-group
    const int d = dbase + (lane >> 3);
    const int n0 = li * 2;

    const float LOG2E = 1.44269504f;
    const float An0 = -__expf(A_log[d * 16 + n0])     * LOG2E;
    const float An1 = -__expf(A_log[d * 16 + n0 + 1]) * LOG2E;

    const float4* vp  = g_scanin + (size_t)(b * 2048) * 512 + d;
    const float4* bcp = reinterpret_cast<const float4*>(g_bc)
                        + (size_t)(b * 2048) * 8 + li;
    float* yp = g_y + (size_t)(b * 2048) * 512 + d;

    float h0 = 0.f, h1 = 0.f;
#pragma unroll 2
    for (int t = 0; t < 2048; ++t) {
        float4 v  = vp[(size_t)t * 512];   // (delta, delta*xc, silu(z), xc*D)
        float4 bc = bcp[(size_t)t * 8];    // (B_n0, C_n0, B_n0+1, C_n0+1)
        float dA0 = exp2f(v.x * An0);
        float dA1 = exp2f(v.x * An1);
        h0 = fmaf(dA0, h0, v.y * bc.x);
        h1 = fmaf(dA1, h1, v.y * bc.z);
        float p = fmaf(h0, bc.y, h1 * bc.w);
        p += __shfl_xor_sync(0xffffffffu, p, 1);
        p += __shfl_xor_sync(0xffffffffu, p, 2);
        p += __shfl_xor_sync(0xffffffffu, p, 4);
        if (li == 0)
            yp[(size_t)t * 512] = (p + v.w) * v.z;
    }
}

// ------------------------- LayerNorm stats + apply ------------------------
__global__ void stats_kernel()
{
    int b = threadIdx.x;
    if (b >= BATCH) return;
    double s = 0.0, ss = 0.0;
    for (int bm = b * 16; bm < b * 16 + 16; ++bm)
        for (int bn = 0; bn < 2; ++bn) {
            int pid = bm * 2 + bn;
            s  += (double)g_psum[2 * pid];
            ss += (double)g_psum[2 * pid + 1];
        }
    const double nd = (double)LSEQ * NOUT;
    double mu = s / nd;
    double var = ss / nd - mu * mu;
    g_stats[b] = make_float2((float)mu, (float)rsqrt(var + 1e-5));
}

__global__ void __launch_bounds__(256)
norm_kernel(float* __restrict__ out, const float* __restrict__ lnw,
            const float* __restrict__ lnb)
{
    size_t i4 = (size_t)blockIdx.x * 256 + threadIdx.x;
    size_t base = i4 * 4;
    int row = (int)(base >> 8);
    int b = row >> 11;
    int l = row & 2047;
    int o = (int)(base & 255);
    float2 st = g_stats[b];
    float4 v = *(float4*)(out + base);
    const float4 w  = *(const float4*)(lnw + (size_t)l * 256 + o);
    const float4 bb = *(const float4*)(lnb + (size_t)l * 256 + o);
    v.x = (v.x - st.x) * st.y * w.x + bb.x;
    v.y = (v.y - st.x) * st.y * w.y + bb.y;
    v.z = (v.z - st.x) * st.y * w.z + bb.z;
    v.w = (v.w - st.x) * st.y * w.w + bb.w;
    *(float4*)(out + base) = v;
}

// ------------------------------- launch -----------------------------------
extern "C" void kernel_launch(void* const* d_in, const int* in_sizes, int n_in,
                              void* d_out, int out_size)
{
    const float* inputs    = (const float*)d_in[0];
    const float* in_proj_w = (const float*)d_in[1];
    const float* conv_w    = (const float*)d_in[2];
    const float* conv_b    = (const float*)d_in[3];
    const float* x_proj_w  = (const float*)d_in[4];
    const float* dt_proj_w = (const float*)d_in[5];
    const float* dt_proj_b = (const float*)d_in[6];
    const float* A_log     = (const float*)d_in[7];
    const float* D_skip    = (const float*)d_in[8];
    const float* out_proj_w= (const float*)d_in[9];
    const float* dim_w     = (const float*)d_in[10];
    const float* dim_b     = (const float*)d_in[11];
    const float* ln_w      = (const float*)d_in[12];
    const float* ln_b      = (const float*)d_in[13];
    float* out = (float*)d_out;

    float *xz, *y, *t1;
    cudaGetSymbolAddress((void**)&xz, g_xz);
    cudaGetSymbolAddress((void**)&y,  g_y);
    cudaGetSymbolAddress((void**)&t1, g_t1);

    // 1) xz = inputs @ in_proj_w^T   [32768 x 1024], silu on z half (bn>=4)
    gemm_nt_kernel<3><<<dim3(1024 / 128, NROWS / 128), 256>>>(
        inputs, in_proj_w, xz, NROWS, 1024, 256, nullptr);

    // 2) conv + silu + x_proj + dt_proj, packed scan inputs (16 tokens/block)
    convproj_kernel<<<NROWS / TOK, 512>>>(conv_w, conv_b, x_proj_w,
                                          dt_proj_w, dt_proj_b, D_skip);

    // 3) selective scan (+D skip, * silu(z))
    scan_kernel<<<512, 128>>>(A_log);

    // 4) t1 = silu(y @ out_proj_w^T)  [32768 x 256]
    gemm_nt_kernel<1><<<dim3(256 / 128, NROWS / 128), 256>>>(
        y, out_proj_w, t1, NROWS, 256, 512, nullptr);

    // 5) out = t1 @ dim_w^T + dim_b, plus per-block partial sums
    gemm_nt_kernel<2><<<dim3(256 / 128, NROWS / 128), 256>>>(
        t1, dim_w, out, NROWS, 256, 256, dim_b);

    // 6) per-batch LayerNorm over (L, N_OUT)
    stats_kernel<<<1, 32>>>();
    norm_kernel<<<(NROWS * NOUT / 4) / 256, 256>>>(out, ln_w, ln_b);
}

// round 3
// speedup vs baseline: 1.8849x; 1.8849x over previous
#include <cuda_runtime.h>
#include <math.h>

#define BATCH   16
#define LSEQ    2048
#define DMODEL  256
#define DINNER  512
#define DSTATE  16
#define NOUT    256
#define NROWS   (BATCH*LSEQ)   /* 32768 */

// ---------------- device scratch (no allocations allowed) ----------------
__device__ float  g_xz[(size_t)NROWS * 1024];        // in_proj output (x | silu(z))
__device__ float4 g_scanin[(size_t)NROWS * DINNER];  // (delta, delta*xc, silu(z), xc*D)
__device__ float2 g_bc[(size_t)NROWS * DSTATE];      // (B_n, C_n) interleaved
__device__ float  g_y[(size_t)NROWS * DINNER];       // scan output (pre out_proj)
__device__ float  g_t1[(size_t)NROWS * NOUT];        // silu(out_proj)
__device__ float  g_psum[512 * 2];                   // per-block (sum, sumsq)
__device__ float2 g_stats[BATCH];                    // (mean, rstd)

__device__ __forceinline__ float silu_f(float v) {
    return v / (1.f + __expf(-v));
}

// ---------------- NT SGEMM: C[M,N] = A[M,K] * B[N,K]^T --------------------
// Round-1 single-buffered body (97 regs, no spills, 34 TF/s measured).
// EPI: 0 = plain, 1 = silu, 2 = +bias + per-block (sum,sumsq)->g_psum,
//      3 = silu only on column-blocks bn>=4 (z half of in_proj output)
template <int EPI>
__global__ void __launch_bounds__(256)
gemm_nt_kernel(const float* __restrict__ A, const float* __restrict__ B,
               float* __restrict__ C, int M, int N, int K,
               const float* __restrict__ bias)
{
    __shared__ float As[8][128];
    __shared__ float Bs[8][128];
    __shared__ float rs[256];
    __shared__ float rss[256];

    const int tid = threadIdx.x;
    const int bm = blockIdx.y, bn = blockIdx.x;

    const int lrow = tid >> 1;          // 0..127
    const int lcol = (tid & 1) * 4;     // 0 or 4
    const float* Ag = A + (size_t)(bm * 128 + lrow) * K + lcol;
    const float* Bg = B + (size_t)(bn * 128 + lrow) * K + lcol;

    const int tm = (tid >> 4) * 8;
    const int tn = (tid & 15) * 8;

    float c[8][8] = {};

    const int nk = K / 8;
    for (int kt = 0; kt < nk; ++kt) {
        float4 av = *(const float4*)(Ag + kt * 8);
        float4 bv = *(const float4*)(Bg + kt * 8);
        As[lcol + 0][lrow] = av.x; As[lcol + 1][lrow] = av.y;
        As[lcol + 2][lrow] = av.z; As[lcol + 3][lrow] = av.w;
        Bs[lcol + 0][lrow] = bv.x; Bs[lcol + 1][lrow] = bv.y;
        Bs[lcol + 2][lrow] = bv.z; Bs[lcol + 3][lrow] = bv.w;
        __syncthreads();
#pragma unroll
        for (int k = 0; k < 8; ++k) {
            float4 a0 = *(const float4*)&As[k][tm];
            float4 a1 = *(const float4*)&As[k][tm + 4];
            float4 b0 = *(const float4*)&Bs[k][tn];
            float4 b1 = *(const float4*)&Bs[k][tn + 4];
            float a[8] = {a0.x,a0.y,a0.z,a0.w,a1.x,a1.y,a1.z,a1.w};
            float b[8] = {b0.x,b0.y,b0.z,b0.w,b1.x,b1.y,b1.z,b1.w};
#pragma unroll
            for (int i = 0; i < 8; ++i)
#pragma unroll
                for (int j = 0; j < 8; ++j)
                    c[i][j] = fmaf(a[i], b[j], c[i][j]);
        }
        __syncthreads();
    }

    float s = 0.f, ss = 0.f;
    const bool do_silu = (EPI == 1) || (EPI == 3 && bn >= 4);
#pragma unroll
    for (int i = 0; i < 8; ++i) {
        float* Crow = C + (size_t)(bm * 128 + tm + i) * N + bn * 128 + tn;
#pragma unroll
        for (int j = 0; j < 8; j += 4) {
            float v[4];
#pragma unroll
            for (int q = 0; q < 4; ++q) {
                float x = c[i][j + q];
                if (do_silu) x = silu_f(x);
                if (EPI == 2) {
                    x += bias[bn * 128 + tn + j + q];
                    s += x; ss += x * x;
                }
                v[q] = x;
            }
            *(float4*)(Crow + j) = make_float4(v[0], v[1], v[2], v[3]);
        }
    }

    if (EPI == 2) {
        rs[tid] = s; rss[tid] = ss;
        __syncthreads();
        for (int off = 128; off > 0; off >>= 1) {
            if (tid < off) { rs[tid] += rs[tid + off]; rss[tid] += rss[tid + off]; }
            __syncthreads();
        }
        if (tid == 0) {
            int pid = bm * gridDim.x + bn;
            g_psum[2 * pid] = rs[0];
            g_psum[2 * pid + 1] = rss[0];
        }
    }
}

// ---------- fused causal conv + SiLU + x_proj + dt_proj + pack -----------
// one block = 16 tokens x 512 channels; 512 threads (one per channel)
#define TOK 16
__global__ void __launch_bounds__(512)
convproj_kernel(const float* __restrict__ conv_w, const float* __restrict__ conv_b,
                const float* __restrict__ x_proj_w, const float* __restrict__ dt_proj_w,
                const float* __restrict__ dt_proj_b, const float* __restrict__ D_skip)
{
    const int b  = blockIdx.x >> 7;
    const int l0 = (blockIdx.x & 127) * TOK;
    const int d  = threadIdx.x;

    __shared__ float xc_s[TOK][512];
    __shared__ float xdbl_s[TOK][48];

    // ---- causal depthwise conv (D_CONV=4) with register sliding window ----
    {
        float4 cw = ((const float4*)conv_w)[d];
        float cb = conv_b[d];
        const float* xcol = g_xz + (size_t)(b * 2048 + l0) * 1024 + d;
        float w0 = (l0 - 3 >= 0) ? xcol[-3 * 1024] : 0.f;
        float w1 = (l0 - 2 >= 0) ? xcol[-2 * 1024] : 0.f;
        float w2 = (l0 - 1 >= 0) ? xcol[-1 * 1024] : 0.f;
#pragma unroll
        for (int t = 0; t < TOK; ++t) {
            float cur = xcol[t * 1024];
            float acc = cb;
            acc = fmaf(w0, cw.x, acc);
            acc = fmaf(w1, cw.y, acc);
            acc = fmaf(w2, cw.z, acc);
            acc = fmaf(cur, cw.w, acc);
            xc_s[t][d] = silu_f(acc);
            w0 = w1; w1 = w2; w2 = cur;
        }
    }
    __syncthreads();

    // ---- x_dbl[t][48] = xc[t] . x_proj_w^T : 16 warps x 3 outputs --------
    {
        const int warp = d >> 5, lane = d & 31;
        float4 wv[3][4];
        const float4* xw4 = (const float4*)x_proj_w;
#pragma unroll
        for (int jj = 0; jj < 3; ++jj) {
            const float4* wrow = xw4 + (size_t)(warp * 3 + jj) * 128;
#pragma unroll
            for (int q = 0; q < 4; ++q)
                wv[jj][q] = wrow[lane + q * 32];
        }
#pragma unroll
        for (int t = 0; t < TOK; ++t) {
            float4 xv[4];
            const float4* xr = (const float4*)&xc_s[t][0];
#pragma unroll
            for (int q = 0; q < 4; ++q) xv[q] = xr[lane + q * 32];
            float a0 = 0.f, a1 = 0.f, a2 = 0.f;
#pragma unroll
            for (int q = 0; q < 4; ++q) {
                a0 = fmaf(xv[q].x, wv[0][q].x, a0); a0 = fmaf(xv[q].y, wv[0][q].y, a0);
                a0 = fmaf(xv[q].z, wv[0][q].z, a0); a0 = fmaf(xv[q].w, wv[0][q].w, a0);
                a1 = fmaf(xv[q].x, wv[1][q].x, a1); a1 = fmaf(xv[q].y, wv[1][q].y, a1);
                a1 = fmaf(xv[q].z, wv[1][q].z, a1); a1 = fmaf(xv[q].w, wv[1][q].w, a1);
                a2 = fmaf(xv[q].x, wv[2][q].x, a2); a2 = fmaf(xv[q].y, wv[2][q].y, a2);
                a2 = fmaf(xv[q].z, wv[2][q].z, a2); a2 = fmaf(xv[q].w, wv[2][q].w, a2);
            }
#pragma unroll
            for (int off = 16; off; off >>= 1) {
                a0 += __shfl_xor_sync(0xffffffffu, a0, off);
                a1 += __shfl_xor_sync(0xffffffffu, a1, off);
                a2 += __shfl_xor_sync(0xffffffffu, a2, off);
            }
            if (lane == 0) {
                xdbl_s[t][warp * 3 + 0] = a0;
                xdbl_s[t][warp * 3 + 1] = a1;
                xdbl_s[t][warp * 3 + 2] = a2;
            }
        }
    }
    __syncthreads();

    // ---- delta = softplus(dt @ dt_proj_w^T + b), pack scan inputs --------
    {
        const float4* dw = (const float4*)(dt_proj_w + d * 16);
        float4 dw0 = dw[0], dw1 = dw[1], dw2 = dw[2], dw3 = dw[3];
        const float dtb = dt_proj_b[d];
        const float Dv = D_skip[d];
        const float* zptr = g_xz + (size_t)(b * 2048 + l0) * 1024 + 512 + d;
        float4* outp = g_scanin + (size_t)(b * 2048 + l0) * 512 + d;
#pragma unroll
        for (int t = 0; t < TOK; ++t) {
            const float4* xr = (const float4*)&xdbl_s[t][0];
            float4 x0 = xr[0], x1 = xr[1], x2 = xr[2], x3 = xr[3];
            float dt = dtb;
            dt = fmaf(x0.x, dw0.x, dt); dt = fmaf(x0.y, dw0.y, dt);
            dt = fmaf(x0.z, dw0.z, dt); dt = fmaf(x0.w, dw0.w, dt);
            dt = fmaf(x1.x, dw1.x, dt); dt = fmaf(x1.y, dw1.y, dt);
            dt = fmaf(x1.z, dw1.z, dt); dt = fmaf(x1.w, dw1.w, dt);
            dt = fmaf(x2.x, dw2.x, dt); dt = fmaf(x2.y, dw2.y, dt);
            dt = fmaf(x2.z, dw2.z, dt); dt = fmaf(x2.w, dw2.w, dt);
            dt = fmaf(x3.x, dw3.x, dt); dt = fmaf(x3.y, dw3.y, dt);
            dt = fmaf(x3.z, dw3.z, dt); dt = fmaf(x3.w, dw3.w, dt);
            float delta = (dt > 20.f) ? dt : log1pf(__expf(dt));
            float xc = xc_s[t][d];
            float sz = zptr[(size_t)t * 1024];   // already silu'd by gemm<3>
            outp[(size_t)t * 512] = make_float4(delta, delta * xc, sz, xc * Dv);
        }
    }

    // ---- B, C pack: g_bc[row][n] = (B_n, C_n) ----------------------------
    if (d < TOK * DSTATE) {
        const int t = d >> 4, n = d & 15;
        g_bc[(size_t)(b * 2048 + l0 + t) * 16 + n] =
            make_float2(xdbl_s[t][16 + n], xdbl_s[t][32 + n]);
    }
}

// ---------------------- diagonal selective scan ---------------------------
// warp = 4 channels (d) x 8 lanes x 2 states/lane; 2048 warps total.
// Depth-8 batched register prefetch: 16 independent LDG.128 per batch (MLP=16)
// so the per-warp serial chain pays ~1 DRAM latency per 8 steps.
#define SB 8
__global__ void __launch_bounds__(128)
scan_kernel(const float* __restrict__ A_log)
{
    const int w = blockIdx.x * 4 + (threadIdx.x >> 5);  // 0..2047
    const int b = w >> 7;
    const int dbase = (w & 127) * 4;
    const int lane = threadIdx.x & 31;
    const int li = lane & 7;             // lane within d-group
    const int d = dbase + (lane >> 3);
    const int n0 = li * 2;

    const float LOG2E = 1.44269504f;
    const float An0 = -__expf(A_log[d * 16 + n0])     * LOG2E;
    const float An1 = -__expf(A_log[d * 16 + n0 + 1]) * LOG2E;

    const float4* vp  = g_scanin + (size_t)(b * 2048) * 512 + d;
    const float4* bcp = reinterpret_cast<const float4*>(g_bc)
                        + (size_t)(b * 2048) * 8 + li;
    float* yp = g_y + (size_t)(b * 2048) * 512 + d;

    float h0 = 0.f, h1 = 0.f;
    for (int tb = 0; tb < 2048; tb += SB) {
        float4 vb[SB], bb[SB];
#pragma unroll
        for (int j = 0; j < SB; ++j) vb[j] = vp[(size_t)(tb + j) * 512];
#pragma unroll
        for (int j = 0; j < SB; ++j) bb[j] = bcp[(size_t)(tb + j) * 8];
#pragma unroll
        for (int j = 0; j < SB; ++j) {
            float4 v  = vb[j];   // (delta, delta*xc, silu(z), xc*D)
            float4 bc = bb[j];   // (B_n0, C_n0, B_n0+1, C_n0+1)
            float dA0 = exp2f(v.x * An0);
            float dA1 = exp2f(v.x * An1);
            h0 = fmaf(dA0, h0, v.y * bc.x);
            h1 = fmaf(dA1, h1, v.y * bc.z);
            float p = fmaf(h0, bc.y, h1 * bc.w);
            p += __shfl_xor_sync(0xffffffffu, p, 1);
            p += __shfl_xor_sync(0xffffffffu, p, 2);
            p += __shfl_xor_sync(0xffffffffu, p, 4);
            if (li == 0)
                yp[(size_t)(tb + j) * 512] = (p + v.w) * v.z;
        }
    }
}

// ------------------------- LayerNorm stats + apply ------------------------
__global__ void stats_kernel()
{
    int b = threadIdx.x;
    if (b >= BATCH) return;
    double s = 0.0, ss = 0.0;
    for (int bm = b * 16; bm < b * 16 + 16; ++bm)
        for (int bn = 0; bn < 2; ++bn) {
            int pid = bm * 2 + bn;
            s  += (double)g_psum[2 * pid];
            ss += (double)g_psum[2 * pid + 1];
        }
    const double nd = (double)LSEQ * NOUT;
    double mu = s / nd;
    double var = ss / nd - mu * mu;
    g_stats[b] = make_float2((float)mu, (float)rsqrt(var + 1e-5));
}

__global__ void __launch_bounds__(256)
norm_kernel(float* __restrict__ out, const float* __restrict__ lnw,
            const float* __restrict__ lnb)
{
    size_t i4 = (size_t)blockIdx.x * 256 + threadIdx.x;
    size_t base = i4 * 4;
    int row = (int)(base >> 8);
    int b = row >> 11;
    int l = row & 2047;
    int o = (int)(base & 255);
    float2 st = g_stats[b];
    float4 v = *(float4*)(out + base);
    const float4 w  = *(const float4*)(lnw + (size_t)l * 256 + o);
    const float4 bb = *(const float4*)(lnb + (size_t)l * 256 + o);
    v.x = (v.x - st.x) * st.y * w.x + bb.x;
    v.y = (v.y - st.x) * st.y * w.y + bb.y;
    v.z = (v.z - st.x) * st.y * w.z + bb.z;
    v.w = (v.w - st.x) * st.y * w.w + bb.w;
    *(float4*)(out + base) = v;
}

// ------------------------------- launch -----------------------------------
extern "C" void kernel_launch(void* const* d_in, const int* in_sizes, int n_in,
                              void* d_out, int out_size)
{
    const float* inputs    = (const float*)d_in[0];
    const float* in_proj_w = (const float*)d_in[1];
    const float* conv_w    = (const float*)d_in[2];
    const float* conv_b    = (const float*)d_in[3];
    const float* x_proj_w  = (const float*)d_in[4];
    const float* dt_proj_w = (const float*)d_in[5];
    const float* dt_proj_b = (const float*)d_in[6];
    const float* A_log     = (const float*)d_in[7];
    const float* D_skip    = (const float*)d_in[8];
    const float* out_proj_w= (const float*)d_in[9];
    const float* dim_w     = (const float*)d_in[10];
    const float* dim_b     = (const float*)d_in[11];
    const float* ln_w      = (const float*)d_in[12];
    const float* ln_b      = (const float*)d_in[13];
    float* out = (float*)d_out;

    float *xz, *y, *t1;
    cudaGetSymbolAddress((void**)&xz, g_xz);
    cudaGetSymbolAddress((void**)&y,  g_y);
    cudaGetSymbolAddress((void**)&t1, g_t1);

    // 1) xz = inputs @ in_proj_w^T   [32768 x 1024], silu on z half (bn>=4)
    gemm_nt_kernel<3><<<dim3(1024 / 128, NROWS / 128), 256>>>(
        inputs, in_proj_w, xz, NROWS, 1024, 256, nullptr);

    // 2) conv + silu + x_proj + dt_proj, packed scan inputs (16 tokens/block)
    convproj_kernel<<<NROWS / TOK, 512>>>(conv_w, conv_b, x_proj_w,
                                          dt_proj_w, dt_proj_b, D_skip);

    // 3) selective scan (+D skip, * silu(z))
    scan_kernel<<<512, 128>>>(A_log);

    // 4) t1 = silu(y @ out_proj_w^T)  [32768 x 256]
    gemm_nt_kernel<1><<<dim3(256 / 128, NROWS / 128), 256>>>(
        y, out_proj_w, t1, NROWS, 256, 512, nullptr);

    // 5) out = t1 @ dim_w^T + dim_b, plus per-block partial sums
    gemm_nt_kernel<2><<<dim3(256 / 128, NROWS / 128), 256>>>(
        t1, dim_w, out, NROWS, 256, 256, dim_b);

    // 6) per-batch LayerNorm over (L, N_OUT)
    stats_kernel<<<1, 32>>>();
    norm_kernel<<<(NROWS * NOUT / 4) / 256, 256>>>(out, ln_w, ln_b);
}

// round 5
// speedup vs baseline: 2.1777x; 1.1554x over previous
#include <cuda_runtime.h>
#include <math.h>
#include <stdint.h>

#define BATCH   16
#define LSEQ    2048
#define DMODEL  256
#define DINNER  512
#define DSTATE  16
#define NOUT    256
#define NROWS   (BATCH*LSEQ)   /* 32768 */

// ---------------- device scratch (no allocations allowed) ----------------
__device__ float  g_xz[(size_t)NROWS * 1024];        // in_proj output (x | silu(z))
__device__ float4 g_scanin[(size_t)NROWS * DINNER];  // (delta, delta*xc, silu(z), xc*D)
__device__ float2 g_bc[(size_t)NROWS * DSTATE];      // (B_n, C_n) interleaved
__device__ float  g_y[(size_t)NROWS * DINNER];       // scan output (pre out_proj)
__device__ float  g_t1[(size_t)NROWS * NOUT];        // silu(out_proj)
__device__ float  g_psum[512 * 2];                   // per-block (sum, sumsq)
__device__ float2 g_stats[BATCH];                    // (mean, rstd)

__device__ __forceinline__ float silu_f(float v) {
    return v / (1.f + __expf(-v));
}

// ---------------------------- TF32 helpers --------------------------------
__device__ __forceinline__ uint32_t f2tf32(float x) {
    uint32_t r;
    asm("cvt.rna.tf32.f32 %0, %1;" : "=r"(r) : "f"(x));
    return r;
}
__device__ __forceinline__ void mma_tf32(float* c, const uint32_t* a,
                                         const uint32_t* b) {
    asm volatile(
        "mma.sync.aligned.m16n8k8.row.col.f32.tf32.tf32.f32 "
        "{%0,%1,%2,%3}, {%4,%5,%6,%7}, {%8,%9}, {%0,%1,%2,%3};"
        : "+f"(c[0]), "+f"(c[1]), "+f"(c[2]), "+f"(c[3])
        : "r"(a[0]), "r"(a[1]), "r"(a[2]), "r"(a[3]), "r"(b[0]), "r"(b[1]));
}

// -------------------- 3xTF32 tensor-core NT GEMM --------------------------
// C[M,N] = A[M,K] * B[N,K]^T via hi*hi + a_hi*b_lo + a_lo*b_hi.
// Block 128x128, BK=16, 8 warps (warp tile 64x32), hi/lo split at tile load.
// EPI: 1 = silu, 2 = +bias + per-block psum, 3 = silu on bn>=4 (z half)
#define SSTR 137
template <int EPI>
__global__ void __launch_bounds__(256, 2)
gemm_tf32_kernel(const float* __restrict__ A, const float* __restrict__ B,
                 float* __restrict__ C, int N, int K,
                 const float* __restrict__ bias)
{
    __shared__ uint32_t Ah[16][SSTR], Al[16][SSTR];
    __shared__ uint32_t Bh[16][SSTR], Bl[16][SSTR];
    __shared__ float red_s[256], red_ss[256];

    const int tid = threadIdx.x;
    const int wid = tid >> 5;
    const int lane = tid & 31;
    const int grp = lane >> 2;       // 0..7
    const int tg  = lane & 3;        // 0..3
    const int warp_m = wid & 1;      // 2 x 64 rows
    const int warp_n = wid >> 1;     // 4 x 32 cols
    const int bm = blockIdx.y, bn = blockIdx.x;

    const int lrow = tid >> 2;       // 0..63
    const int lkq  = tid & 3;        // k-quad

    float acc[4][4][4] = {};

    const int nkt = K >> 4;
    for (int kt = 0; kt < nkt; ++kt) {
        // ---- load 128x16 fp32 tiles, split to tf32 hi/lo in smem ----
        __syncthreads();
#pragma unroll
        for (int rr = 0; rr < 2; ++rr) {
            const int r = lrow + rr * 64;
            float4 va = *(const float4*)(A + (size_t)(bm * 128 + r) * K +
                                         kt * 16 + lkq * 4);
            float4 vb = *(const float4*)(B + (size_t)(bn * 128 + r) * K +
                                         kt * 16 + lkq * 4);
            const float av[4] = {va.x, va.y, va.z, va.w};
            const float bv[4] = {vb.x, vb.y, vb.z, vb.w};
#pragma unroll
            for (int q = 0; q < 4; ++q) {
                const int k = lkq * 4 + q;
                uint32_t h = f2tf32(av[q]);
                Ah[k][r] = h;
                Al[k][r] = f2tf32(av[q] - __uint_as_float(h));
                h = f2tf32(bv[q]);
                Bh[k][r] = h;
                Bl[k][r] = f2tf32(bv[q] - __uint_as_float(h));
            }
        }
        __syncthreads();

        // ---- 2 k8 steps, 3 passes each ----
#pragma unroll
        for (int k8 = 0; k8 < 2; ++k8) {
            const int k0 = k8 * 8;
            uint32_t ah[4][4], bh[4][2], bl[4][2];
#pragma unroll
            for (int mi = 0; mi < 4; ++mi) {
                const int m = warp_m * 64 + mi * 16 + grp;
                ah[mi][0] = Ah[k0 + tg][m];
                ah[mi][1] = Ah[k0 + tg][m + 8];
                ah[mi][2] = Ah[k0 + tg + 4][m];
                ah[mi][3] = Ah[k0 + tg + 4][m + 8];
            }
#pragma unroll
            for (int ni = 0; ni < 4; ++ni) {
                const int n = warp_n * 32 + ni * 8 + grp;
                bh[ni][0] = Bh[k0 + tg][n];
                bh[ni][1] = Bh[k0 + tg + 4][n];
            }
#pragma unroll
            for (int mi = 0; mi < 4; ++mi)
#pragma unroll
                for (int ni = 0; ni < 4; ++ni)
                    mma_tf32(acc[mi][ni], ah[mi], bh[ni]);
#pragma unroll
            for (int ni = 0; ni < 4; ++ni) {
                const int n = warp_n * 32 + ni * 8 + grp;
                bl[ni][0] = Bl[k0 + tg][n];
                bl[ni][1] = Bl[k0 + tg + 4][n];
            }
#pragma unroll
            for (int mi = 0; mi < 4; ++mi)
#pragma unroll
                for (int ni = 0; ni < 4; ++ni)
                    mma_tf32(acc[mi][ni], ah[mi], bl[ni]);
#pragma unroll
            for (int mi = 0; mi < 4; ++mi) {
                const int m = warp_m * 64 + mi * 16 + grp;
                ah[mi][0] = Al[k0 + tg][m];
                ah[mi][1] = Al[k0 + tg][m + 8];
                ah[mi][2] = Al[k0 + tg + 4][m];
                ah[mi][3] = Al[k0 + tg + 4][m + 8];
            }
#pragma unroll
            for (int mi = 0; mi < 4; ++mi)
#pragma unroll
                for (int ni = 0; ni < 4; ++ni)
                    mma_tf32(acc[mi][ni], ah[mi], bh[ni]);
        }
    }

    // ------------------------------ epilogue ------------------------------
    float s = 0.f, ss = 0.f;
    const bool dos = (EPI == 1) || (EPI == 3 && bn >= 4);
#pragma unroll
    for (int mi = 0; mi < 4; ++mi) {
        const int row0 = bm * 128 + warp_m * 64 + mi * 16 + grp;
#pragma unroll
        for (int ni = 0; ni < 4; ++ni) {
            const int col = bn * 128 + warp_n * 32 + ni * 8 + tg * 2;
            float v0 = acc[mi][ni][0], v1 = acc[mi][ni][1];
            float v2 = acc[mi][ni][2], v3 = acc[mi][ni][3];
            if (dos) { v0 = silu_f(v0); v1 = silu_f(v1);
                       v2 = silu_f(v2); v3 = silu_f(v3); }
            if (EPI == 2) {
                const float b0 = bias[col], b1 = bias[col + 1];
                v0 += b0; v1 += b1; v2 += b0; v3 += b1;
                s += v0 + v1 + v2 + v3;
                ss += v0 * v0 + v1 * v1 + v2 * v2 + v3 * v3;
            }
            *(float2*)(C + (size_t)row0 * N + col)       = make_float2(v0, v1);
            *(float2*)(C + (size_t)(row0 + 8) * N + col) = make_float2(v2, v3);
        }
    }

    if (EPI == 2) {
        red_s[tid] = s; red_ss[tid] = ss;
        __syncthreads();
        for (int off = 128; off > 0; off >>= 1) {
            if (tid < off) { red_s[tid] += red_s[tid + off];
                             red_ss[tid] += red_ss[tid + off]; }
            __syncthreads();
        }
        if (tid == 0) {
            int pid = bm * gridDim.x + bn;
            g_psum[2 * pid] = red_s[0];
            g_psum[2 * pid + 1] = red_ss[0];
        }
    }
}

// ---------- fused causal conv + SiLU + x_proj + dt_proj + pack -----------
#define TOK 16
__global__ void __launch_bounds__(512)
convproj_kernel(const float* __restrict__ conv_w, const float* __restrict__ conv_b,
                const float* __restrict__ x_proj_w, const float* __restrict__ dt_proj_w,
                const float* __restrict__ dt_proj_b, const float* __restrict__ D_skip)
{
    const int b  = blockIdx.x >> 7;
    const int l0 = (blockIdx.x & 127) * TOK;
    const int d  = threadIdx.x;

    __shared__ float xc_s[TOK][512];
    __shared__ float xdbl_s[TOK][48];

    {
        float4 cw = ((const float4*)conv_w)[d];
        float cb = conv_b[d];
        const float* xcol = g_xz + (size_t)(b * 2048 + l0) * 1024 + d;
        float w0 = (l0 - 3 >= 0) ? xcol[-3 * 1024] : 0.f;
        float w1 = (l0 - 2 >= 0) ? xcol[-2 * 1024] : 0.f;
        float w2 = (l0 - 1 >= 0) ? xcol[-1 * 1024] : 0.f;
#pragma unroll
        for (int t = 0; t < TOK; ++t) {
            float cur = xcol[t * 1024];
            float acc = cb;
            acc = fmaf(w0, cw.x, acc);
            acc = fmaf(w1, cw.y, acc);
            acc = fmaf(w2, cw.z, acc);
            acc = fmaf(cur, cw.w, acc);
            xc_s[t][d] = silu_f(acc);
            w0 = w1; w1 = w2; w2 = cur;
        }
    }
    __syncthreads();

    {
        const int warp = d >> 5, lane = d & 31;
        float4 wv[3][4];
        const float4* xw4 = (const float4*)x_proj_w;
#pragma unroll
        for (int jj = 0; jj < 3; ++jj) {
            const float4* wrow = xw4 + (size_t)(warp * 3 + jj) * 128;
#pragma unroll
            for (int q = 0; q < 4; ++q)
                wv[jj][q] = wrow[lane + q * 32];
        }
#pragma unroll
        for (int t = 0; t < TOK; ++t) {
            float4 xv[4];
            const float4* xr = (const float4*)&xc_s[t][0];
#pragma unroll
            for (int q = 0; q < 4; ++q) xv[q] = xr[lane + q * 32];
            float a0 = 0.f, a1 = 0.f, a2 = 0.f;
#pragma unroll
            for (int q = 0; q < 4; ++q) {
                a0 = fmaf(xv[q].x, wv[0][q].x, a0); a0 = fmaf(xv[q].y, wv[0][q].y, a0);
                a0 = fmaf(xv[q].z, wv[0][q].z, a0); a0 = fmaf(xv[q].w, wv[0][q].w, a0);
                a1 = fmaf(xv[q].x, wv[1][q].x, a1); a1 = fmaf(xv[q].y, wv[1][q].y, a1);
                a1 = fmaf(xv[q].z, wv[1][q].z, a1); a1 = fmaf(xv[q].w, wv[1][q].w, a1);
                a2 = fmaf(xv[q].x, wv[2][q].x, a2); a2 = fmaf(xv[q].y, wv[2][q].y, a2);
                a2 = fmaf(xv[q].z, wv[2][q].z, a2); a2 = fmaf(xv[q].w, wv[2][q].w, a2);
            }
#pragma unroll
            for (int off = 16; off; off >>= 1) {
                a0 += __shfl_xor_sync(0xffffffffu, a0, off);
                a1 += __shfl_xor_sync(0xffffffffu, a1, off);
                a2 += __shfl_xor_sync(0xffffffffu, a2, off);
            }
            if (lane == 0) {
                xdbl_s[t][warp * 3 + 0] = a0;
                xdbl_s[t][warp * 3 + 1] = a1;
                xdbl_s[t][warp * 3 + 2] = a2;
            }
        }
    }
    __syncthreads();

    {
        const float4* dw = (const float4*)(dt_proj_w + d * 16);
        float4 dw0 = dw[0], dw1 = dw[1], dw2 = dw[2], dw3 = dw[3];
        const float dtb = dt_proj_b[d];
        const float Dv = D_skip[d];
        const float* zptr = g_xz + (size_t)(b * 2048 + l0) * 1024 + 512 + d;
        float4* outp = g_scanin + (size_t)(b * 2048 + l0) * 512 + d;
#pragma unroll
        for (int t = 0; t < TOK; ++t) {
            const float4* xr = (const float4*)&xdbl_s[t][0];
            float4 x0 = xr[0], x1 = xr[1], x2 = xr[2], x3 = xr[3];
            float dt = dtb;
            dt = fmaf(x0.x, dw0.x, dt); dt = fmaf(x0.y, dw0.y, dt);
            dt = fmaf(x0.z, dw0.z, dt); dt = fmaf(x0.w, dw0.w, dt);
            dt = fmaf(x1.x, dw1.x, dt); dt = fmaf(x1.y, dw1.y, dt);
            dt = fmaf(x1.z, dw1.z, dt); dt = fmaf(x1.w, dw1.w, dt);
            dt = fmaf(x2.x, dw2.x, dt); dt = fmaf(x2.y, dw2.y, dt);
            dt = fmaf(x2.z, dw2.z, dt); dt = fmaf(x2.w, dw2.w, dt);
            dt = fmaf(x3.x, dw3.x, dt); dt = fmaf(x3.y, dw3.y, dt);
            dt = fmaf(x3.z, dw3.z, dt); dt = fmaf(x3.w, dw3.w, dt);
            float delta = (dt > 20.f) ? dt : log1pf(__expf(dt));
            float xc = xc_s[t][d];
            float sz = zptr[(size_t)t * 1024];
            outp[(size_t)t * 512] = make_float4(delta, delta * xc, sz, xc * Dv);
        }
    }

    if (d < TOK * DSTATE) {
        const int t = d >> 4, n = d & 15;
        g_bc[(size_t)(b * 2048 + l0 + t) * 16 + n] =
            make_float2(xdbl_s[t][16 + n], xdbl_s[t][32 + n]);
    }
}

// ---------------------- diagonal selective scan ---------------------------
#define SB 8
__global__ void __launch_bounds__(128)
scan_kernel(const float* __restrict__ A_log)
{
    const int w = blockIdx.x * 4 + (threadIdx.x >> 5);
    const int b = w >> 7;
    const int dbase = (w & 127) * 4;
    const int lane = threadIdx.x & 31;
    const int li = lane & 7;
    const int d = dbase + (lane >> 3);
    const int n0 = li * 2;

    const float LOG2E = 1.44269504f;
    const float An0 = -__expf(A_log[d * 16 + n0])     * LOG2E;
    const float An1 = -__expf(A_log[d * 16 + n0 + 1]) * LOG2E;

    const float4* vp  = g_scanin + (size_t)(b * 2048) * 512 + d;
    const float4* bcp = reinterpret_cast<const float4*>(g_bc)
                        + (size_t)(b * 2048) * 8 + li;
    float* yp = g_y + (size_t)(b * 2048) * 512 + d;

    float h0 = 0.f, h1 = 0.f;
    for (int tb = 0; tb < 2048; tb += SB) {
        float4 vb[SB], bb[SB];
#pragma unroll
        for (int j = 0; j < SB; ++j) vb[j] = vp[(size_t)(tb + j) * 512];
#pragma unroll
        for (int j = 0; j < SB; ++j) bb[j] = bcp[(size_t)(tb + j) * 8];
#pragma unroll
        for (int j = 0; j < SB; ++j) {
            float4 v  = vb[j];
            float4 bc = bb[j];
            float dA0 = exp2f(v.x * An0);
            float dA1 = exp2f(v.x * An1);
            h0 = fmaf(dA0, h0, v.y * bc.x);
            h1 = fmaf(dA1, h1, v.y * bc.z);
            float p = fmaf(h0, bc.y, h1 * bc.w);
            p += __shfl_xor_sync(0xffffffffu, p, 1);
            p += __shfl_xor_sync(0xffffffffu, p, 2);
            p += __shfl_xor_sync(0xffffffffu, p, 4);
            if (li == 0)
                yp[(size_t)(tb + j) * 512] = (p + v.w) * v.z;
        }
    }
}

// ------------------------- LayerNorm stats + apply ------------------------
__global__ void stats_kernel()
{
    int b = threadIdx.x;
    if (b >= BATCH) return;
    double s = 0.0, ss = 0.0;
    for (int bm = b * 16; bm < b * 16 + 16; ++bm)
        for (int bn = 0; bn < 2; ++bn) {
            int pid = bm * 2 + bn;
            s  += (double)g_psum[2 * pid];
            ss += (double)g_psum[2 * pid + 1];
        }
    const double nd = (double)LSEQ * NOUT;
    double mu = s / nd;
    double var = ss / nd - mu * mu;
    g_stats[b] = make_float2((float)mu, (float)rsqrt(var + 1e-5));
}

__global__ void __launch_bounds__(256)
norm_kernel(float* __restrict__ out, const float* __restrict__ lnw,
            const float* __restrict__ lnb)
{
    size_t i4 = (size_t)blockIdx.x * 256 + threadIdx.x;
    size_t base = i4 * 4;
    int row = (int)(base >> 8);
    int b = row >> 11;
    int l = row & 2047;
    int o = (int)(base & 255);
    float2 st = g_stats[b];
    float4 v = *(float4*)(out + base);
    const float4 w  = *(const float4*)(lnw + (size_t)l * 256 + o);
    const float4 bb = *(const float4*)(lnb + (size_t)l * 256 + o);
    v.x = (v.x - st.x) * st.y * w.x + bb.x;
    v.y = (v.y - st.x) * st.y * w.y + bb.y;
    v.z = (v.z - st.x) * st.y * w.z + bb.z;
    v.w = (v.w - st.x) * st.y * w.w + bb.w;
    *(float4*)(out + base) = v;
}

// ------------------------------- launch -----------------------------------
extern "C" void kernel_launch(void* const* d_in, const int* in_sizes, int n_in,
                              void* d_out, int out_size)
{
    const float* inputs    = (const float*)d_in[0];
    const float* in_proj_w = (const float*)d_in[1];
    const float* conv_w    = (const float*)d_in[2];
    const float* conv_b    = (const float*)d_in[3];
    const float* x_proj_w  = (const float*)d_in[4];
    const float* dt_proj_w = (const float*)d_in[5];
    const float* dt_proj_b = (const float*)d_in[6];
    const float* A_log     = (const float*)d_in[7];
    const float* D_skip    = (const float*)d_in[8];
    const float* out_proj_w= (const float*)d_in[9];
    const float* dim_w     = (const float*)d_in[10];
    const float* dim_b     = (const float*)d_in[11];
    const float* ln_w      = (const float*)d_in[12];
    const float* ln_b      = (const float*)d_in[13];
    float* out = (float*)d_out;

    float *xz, *y, *t1;
    cudaGetSymbolAddress((void**)&xz, g_xz);
    cudaGetSymbolAddress((void**)&y,  g_y);
    cudaGetSymbolAddress((void**)&t1, g_t1);

    // 1) xz = inputs @ in_proj_w^T  [32768 x 1024], silu on z half (bn>=4)
    gemm_tf32_kernel<3><<<dim3(1024 / 128, NROWS / 128), 256>>>(
        inputs, in_proj_w, xz, 1024, 256, nullptr);

    // 2) conv + silu + x_proj + dt_proj, packed scan inputs
    convproj_kernel<<<NROWS / TOK, 512>>>(conv_w, conv_b, x_proj_w,
                                          dt_proj_w, dt_proj_b, D_skip);

    // 3) selective scan
    scan_kernel<<<512, 128>>>(A_log);

    // 4) t1 = silu(y @ out_proj_w^T)  [32768 x 256]
    gemm_tf32_kernel<1><<<dim3(256 / 128, NROWS / 128), 256>>>(
        y, out_proj_w, t1, 256, 512, nullptr);

    // 5) out = t1 @ dim_w^T + dim_b, + per-block partial sums
    gemm_tf32_kernel<2><<<dim3(256 / 128, NROWS / 128), 256>>>(
        t1, dim_w, out, 256, 256, dim_b);

    // 6) per-batch LayerNorm
    stats_kernel<<<1, 32>>>();
    norm_kernel<<<(NROWS * NOUT / 4) / 256, 256>>>(out, ln_w, ln_b);
}

// round 6
// speedup vs baseline: 2.7667x; 1.2704x over previous
#include <cuda_runtime.h>
#include <math.h>
#include <stdint.h>

#define BATCH   16
#define LSEQ    2048
#define DMODEL  256
#define DINNER  512
#define DSTATE  16
#define NOUT    256
#define NROWS   (BATCH*LSEQ)   /* 32768 */

// ---------------- device scratch (no allocations allowed) ----------------
__device__ float  g_xz[(size_t)NROWS * 1024];        // in_proj output (x | silu(z))
__device__ float4 g_scanin[(size_t)NROWS * DINNER];  // (delta, delta*xc, silu(z), xc*D)
__device__ float2 g_bc[(size_t)NROWS * DSTATE];      // (B_n, C_n) interleaved
__device__ float  g_y[(size_t)NROWS * DINNER];       // scan output (pre out_proj)
__device__ float  g_t1[(size_t)NROWS * NOUT];        // silu(out_proj)
__device__ float  g_psum[512 * 2];                   // per-block (sum, sumsq)
__device__ float2 g_stats[BATCH];                    // (mean, rstd)

__device__ __forceinline__ float silu_f(float v) {
    return v / (1.f + __expf(-v));
}

// ---------------------------- bf16 helpers --------------------------------
__device__ __forceinline__ uint32_t pack_bf16x2(float hi, float lo) {
    uint32_t r;
    asm("cvt.rn.bf16x2.f32 %0, %1, %2;" : "=r"(r) : "f"(hi), "f"(lo));
    return r;
}
__device__ __forceinline__ float lo_f32(uint32_t p) {
    return __uint_as_float(p << 16);
}
__device__ __forceinline__ float hi_f32(uint32_t p) {
    return __uint_as_float(p & 0xffff0000u);
}
__device__ __forceinline__ void mma_bf16(float* c, const uint32_t* a,
                                         const uint32_t* b) {
    asm volatile(
        "mma.sync.aligned.m16n8k16.row.col.f32.bf16.bf16.f32 "
        "{%0,%1,%2,%3}, {%4,%5,%6,%7}, {%8,%9}, {%0,%1,%2,%3};"
        : "+f"(c[0]), "+f"(c[1]), "+f"(c[2]), "+f"(c[3])
        : "r"(a[0]), "r"(a[1]), "r"(a[2]), "r"(a[3]), "r"(b[0]), "r"(b[1]));
}

// -------------------- 3x-bf16 tensor-core NT GEMM -------------------------
// C[M,N] = A[M,K] * B[N,K]^T via hi*hi + a_hi*b_lo + a_lo*b_hi (bf16 splits).
// Block 128x128, BK=16, 8 warps (warp tile 64x32). Smem layout: packed bf16x2
// interleaved as [k2&3][m*2 + (k2>>2)] with row stride 264 u32 -> frag loads
// are conflict-free LDS.64, stores conflict-free STS.32.
// EPI: 1 = silu, 2 = +bias + per-block psum, 3 = silu on bn>=4 (z half)
#define KSTR 264
template <int EPI>
__global__ void __launch_bounds__(256, 2)
gemm_bf16_kernel(const float* __restrict__ A, const float* __restrict__ B,
                 float* __restrict__ C, int N, int K,
                 const float* __restrict__ bias)
{
    __shared__ uint32_t Ah[4][KSTR], Al[4][KSTR];
    __shared__ uint32_t Bh[4][KSTR], Bl[4][KSTR];
    __shared__ float red_s[256], red_ss[256];

    const int tid = threadIdx.x;
    const int wid = tid >> 5;
    const int lane = tid & 31;
    const int grp = lane >> 2;       // 0..7
    const int tg  = lane & 3;        // 0..3
    const int warp_m = wid & 1;      // 2 x 64 rows
    const int warp_n = wid >> 1;     // 4 x 32 cols
    const int bm = blockIdx.y, bn = blockIdx.x;

    const int lrow = tid >> 2;       // 0..63
    const int lkq  = tid & 3;        // k-quad (4 floats each)

    // store slots for this thread's two packed pairs (k2 = lkq*2, lkq*2+1)
    const int k2a = lkq * 2, k2b = lkq * 2 + 1;
    const int sa_row = k2a & 3, sa_kh = k2a >> 2;
    const int sb_row = k2b & 3, sb_kh = k2b >> 2;

    float acc[4][4][4] = {};

    const int nkt = K >> 4;
    for (int kt = 0; kt < nkt; ++kt) {
        __syncthreads();
#pragma unroll
        for (int rr = 0; rr < 2; ++rr) {
            const int r = lrow + rr * 64;
            float4 va = *(const float4*)(A + (size_t)(bm * 128 + r) * K +
                                         kt * 16 + lkq * 4);
            float4 vb = *(const float4*)(B + (size_t)(bn * 128 + r) * K +
                                         kt * 16 + lkq * 4);
            // A split
            uint32_t h01 = pack_bf16x2(va.y, va.x);
            uint32_t h23 = pack_bf16x2(va.w, va.z);
            uint32_t l01 = pack_bf16x2(va.y - hi_f32(h01), va.x - lo_f32(h01));
            uint32_t l23 = pack_bf16x2(va.w - hi_f32(h23), va.z - lo_f32(h23));
            Ah[sa_row][r * 2 + sa_kh] = h01;
            Al[sa_row][r * 2 + sa_kh] = l01;
            Ah[sb_row][r * 2 + sb_kh] = h23;
            Al[sb_row][r * 2 + sb_kh] = l23;
            // B split
            h01 = pack_bf16x2(vb.y, vb.x);
            h23 = pack_bf16x2(vb.w, vb.z);
            l01 = pack_bf16x2(vb.y - hi_f32(h01), vb.x - lo_f32(h01));
            l23 = pack_bf16x2(vb.w - hi_f32(h23), vb.z - lo_f32(h23));
            Bh[sa_row][r * 2 + sa_kh] = h01;
            Bl[sa_row][r * 2 + sa_kh] = l01;
            Bh[sb_row][r * 2 + sb_kh] = h23;
            Bl[sb_row][r * 2 + sb_kh] = l23;
        }
        __syncthreads();

        // fragment loads (LDS.64, conflict-free)
        uint2 af[4][2], bh[4], bl[4];
#pragma unroll
        for (int mi = 0; mi < 4; ++mi) {
            const int m = warp_m * 64 + mi * 16 + grp;
            af[mi][0] = *(const uint2*)&Ah[tg][2 * m];
            af[mi][1] = *(const uint2*)&Ah[tg][2 * (m + 8)];
        }
#pragma unroll
        for (int ni = 0; ni < 4; ++ni) {
            const int n = warp_n * 32 + ni * 8 + grp;
            bh[ni] = *(const uint2*)&Bh[tg][2 * n];
            bl[ni] = *(const uint2*)&Bl[tg][2 * n];
        }
        // pass 1: Ah * Bh,  pass 2: Ah * Bl
#pragma unroll
        for (int mi = 0; mi < 4; ++mi) {
            const uint32_t a[4] = {af[mi][0].x, af[mi][1].x,
                                   af[mi][0].y, af[mi][1].y};
#pragma unroll
            for (int ni = 0; ni < 4; ++ni) {
                const uint32_t b0[2] = {bh[ni].x, bh[ni].y};
                const uint32_t b1[2] = {bl[ni].x, bl[ni].y};
                mma_bf16(acc[mi][ni], a, b0);
                mma_bf16(acc[mi][ni], a, b1);
            }
        }
        // pass 3: Al * Bh (reuse af regs)
#pragma unroll
        for (int mi = 0; mi < 4; ++mi) {
            const int m = warp_m * 64 + mi * 16 + grp;
            af[mi][0] = *(const uint2*)&Al[tg][2 * m];
            af[mi][1] = *(const uint2*)&Al[tg][2 * (m + 8)];
        }
#pragma unroll
        for (int mi = 0; mi < 4; ++mi) {
            const uint32_t a[4] = {af[mi][0].x, af[mi][1].x,
                                   af[mi][0].y, af[mi][1].y};
#pragma unroll
            for (int ni = 0; ni < 4; ++ni) {
                const uint32_t b0[2] = {bh[ni].x, bh[ni].y};
                mma_bf16(acc[mi][ni], a, b0);
            }
        }
    }

    // ------------------------------ epilogue ------------------------------
    float s = 0.f, ss = 0.f;
    const bool dos = (EPI == 1) || (EPI == 3 && bn >= 4);
#pragma unroll
    for (int mi = 0; mi < 4; ++mi) {
        const int row0 = bm * 128 + warp_m * 64 + mi * 16 + grp;
#pragma unroll
        for (int ni = 0; ni < 4; ++ni) {
            const int col = bn * 128 + warp_n * 32 + ni * 8 + tg * 2;
            float v0 = acc[mi][ni][0], v1 = acc[mi][ni][1];
            float v2 = acc[mi][ni][2], v3 = acc[mi][ni][3];
            if (dos) { v0 = silu_f(v0); v1 = silu_f(v1);
                       v2 = silu_f(v2); v3 = silu_f(v3); }
            if (EPI == 2) {
                const float b0 = bias[col], b1 = bias[col + 1];
                v0 += b0; v1 += b1; v2 += b0; v3 += b1;
                s += v0 + v1 + v2 + v3;
                ss += v0 * v0 + v1 * v1 + v2 * v2 + v3 * v3;
            }
            *(float2*)(C + (size_t)row0 * N + col)       = make_float2(v0, v1);
            *(float2*)(C + (size_t)(row0 + 8) * N + col) = make_float2(v2, v3);
        }
    }

    if (EPI == 2) {
        red_s[tid] = s; red_ss[tid] = ss;
        __syncthreads();
        for (int off = 128; off > 0; off >>= 1) {
            if (tid < off) { red_s[tid] += red_s[tid + off];
                             red_ss[tid] += red_ss[tid + off]; }
            __syncthreads();
        }
        if (tid == 0) {
            int pid = bm * gridDim.x + bn;
            g_psum[2 * pid] = red_s[0];
            g_psum[2 * pid + 1] = red_ss[0];
        }
    }
}

// ---------- fused causal conv + SiLU + x_proj + dt_proj + pack -----------
#define TOK 16
__global__ void __launch_bounds__(512)
convproj_kernel(const float* __restrict__ conv_w, const float* __restrict__ conv_b,
                const float* __restrict__ x_proj_w, const float* __restrict__ dt_proj_w,
                const float* __restrict__ dt_proj_b, const float* __restrict__ D_skip)
{
    const int b  = blockIdx.x >> 7;
    const int l0 = (blockIdx.x & 127) * TOK;
    const int d  = threadIdx.x;

    __shared__ float xc_s[TOK][512];
    __shared__ float xdbl_s[TOK][48];

    {
        float4 cw = ((const float4*)conv_w)[d];
        float cb = conv_b[d];
        const float* xcol = g_xz + (size_t)(b * 2048 + l0) * 1024 + d;
        float w0 = (l0 - 3 >= 0) ? xcol[-3 * 1024] : 0.f;
        float w1 = (l0 - 2 >= 0) ? xcol[-2 * 1024] : 0.f;
        float w2 = (l0 - 1 >= 0) ? xcol[-1 * 1024] : 0.f;
#pragma unroll
        for (int t = 0; t < TOK; ++t) {
            float cur = xcol[t * 1024];
            float acc = cb;
            acc = fmaf(w0, cw.x, acc);
            acc = fmaf(w1, cw.y, acc);
            acc = fmaf(w2, cw.z, acc);
            acc = fmaf(cur, cw.w, acc);
            xc_s[t][d] = silu_f(acc);
            w0 = w1; w1 = w2; w2 = cur;
        }
    }
    __syncthreads();

    {
        const int warp = d >> 5, lane = d & 31;
        float4 wv[3][4];
        const float4* xw4 = (const float4*)x_proj_w;
#pragma unroll
        for (int jj = 0; jj < 3; ++jj) {
            const float4* wrow = xw4 + (size_t)(warp * 3 + jj) * 128;
#pragma unroll
            for (int q = 0; q < 4; ++q)
                wv[jj][q] = wrow[lane + q * 32];
        }
#pragma unroll
        for (int t = 0; t < TOK; ++t) {
            float4 xv[4];
            const float4* xr = (const float4*)&xc_s[t][0];
#pragma unroll
            for (int q = 0; q < 4; ++q) xv[q] = xr[lane + q * 32];
            float a0 = 0.f, a1 = 0.f, a2 = 0.f;
#pragma unroll
            for (int q = 0; q < 4; ++q) {
                a0 = fmaf(xv[q].x, wv[0][q].x, a0); a0 = fmaf(xv[q].y, wv[0][q].y, a0);
                a0 = fmaf(xv[q].z, wv[0][q].z, a0); a0 = fmaf(xv[q].w, wv[0][q].w, a0);
                a1 = fmaf(xv[q].x, wv[1][q].x, a1); a1 = fmaf(xv[q].y, wv[1][q].y, a1);
                a1 = fmaf(xv[q].z, wv[1][q].z, a1); a1 = fmaf(xv[q].w, wv[1][q].w, a1);
                a2 = fmaf(xv[q].x, wv[2][q].x, a2); a2 = fmaf(xv[q].y, wv[2][q].y, a2);
                a2 = fmaf(xv[q].z, wv[2][q].z, a2); a2 = fmaf(xv[q].w, wv[2][q].w, a2);
            }
#pragma unroll
            for (int off = 16; off; off >>= 1) {
                a0 += __shfl_xor_sync(0xffffffffu, a0, off);
                a1 += __shfl_xor_sync(0xffffffffu, a1, off);
                a2 += __shfl_xor_sync(0xffffffffu, a2, off);
            }
            if (lane == 0) {
                xdbl_s[t][warp * 3 + 0] = a0;
                xdbl_s[t][warp * 3 + 1] = a1;
                xdbl_s[t][warp * 3 + 2] = a2;
            }
        }
    }
    __syncthreads();

    {
        const float4* dw = (const float4*)(dt_proj_w + d * 16);
        float4 dw0 = dw[0], dw1 = dw[1], dw2 = dw[2], dw3 = dw[3];
        const float dtb = dt_proj_b[d];
        const float Dv = D_skip[d];
        const float* zptr = g_xz + (size_t)(b * 2048 + l0) * 1024 + 512 + d;
        float4* outp = g_scanin + (size_t)(b * 2048 + l0) * 512 + d;
#pragma unroll
        for (int t = 0; t < TOK; ++t) {
            const float4* xr = (const float4*)&xdbl_s[t][0];
            float4 x0 = xr[0], x1 = xr[1], x2 = xr[2], x3 = xr[3];
            float dt = dtb;
            dt = fmaf(x0.x, dw0.x, dt); dt = fmaf(x0.y, dw0.y, dt);
            dt = fmaf(x0.z, dw0.z, dt); dt = fmaf(x0.w, dw0.w, dt);
            dt = fmaf(x1.x, dw1.x, dt); dt = fmaf(x1.y, dw1.y, dt);
            dt = fmaf(x1.z, dw1.z, dt); dt = fmaf(x1.w, dw1.w, dt);
            dt = fmaf(x2.x, dw2.x, dt); dt = fmaf(x2.y, dw2.y, dt);
            dt = fmaf(x2.z, dw2.z, dt); dt = fmaf(x2.w, dw2.w, dt);
            dt = fmaf(x3.x, dw3.x, dt); dt = fmaf(x3.y, dw3.y, dt);
            dt = fmaf(x3.z, dw3.z, dt); dt = fmaf(x3.w, dw3.w, dt);
            float delta = (dt > 20.f) ? dt : __logf(1.f + __expf(dt));
            float xc = xc_s[t][d];
            float sz = zptr[(size_t)t * 1024];
            outp[(size_t)t * 512] = make_float4(delta, delta * xc, sz, xc * Dv);
        }
    }

    if (d < TOK * DSTATE) {
        const int t = d >> 4, n = d & 15;
        g_bc[(size_t)(b * 2048 + l0 + t) * 16 + n] =
            make_float2(xdbl_s[t][16 + n], xdbl_s[t][32 + n]);
    }
}

// ---------------------- diagonal selective scan ---------------------------
#define SB 8
__global__ void __launch_bounds__(128)
scan_kernel(const float* __restrict__ A_log)
{
    const int w = blockIdx.x * 4 + (threadIdx.x >> 5);
    const int b = w >> 7;
    const int dbase = (w & 127) * 4;
    const int lane = threadIdx.x & 31;
    const int li = lane & 7;
    const int d = dbase + (lane >> 3);
    const int n0 = li * 2;

    const float LOG2E = 1.44269504f;
    const float An0 = -__expf(A_log[d * 16 + n0])     * LOG2E;
    const float An1 = -__expf(A_log[d * 16 + n0 + 1]) * LOG2E;

    const float4* vp  = g_scanin + (size_t)(b * 2048) * 512 + d;
    const float4* bcp = reinterpret_cast<const float4*>(g_bc)
                        + (size_t)(b * 2048) * 8 + li;
    float* yp = g_y + (size_t)(b * 2048) * 512 + d;

    float h0 = 0.f, h1 = 0.f;
    for (int tb = 0; tb < 2048; tb += SB) {
        float4 vb[SB], bb[SB];
#pragma unroll
        for (int j = 0; j < SB; ++j) vb[j] = vp[(size_t)(tb + j) * 512];
#pragma unroll
        for (int j = 0; j < SB; ++j) bb[j] = bcp[(size_t)(tb + j) * 8];
#pragma unroll
        for (int j = 0; j < SB; ++j) {
            float4 v  = vb[j];
            float4 bc = bb[j];
            float dA0 = exp2f(v.x * An0);
            float dA1 = exp2f(v.x * An1);
            h0 = fmaf(dA0, h0, v.y * bc.x);
            h1 = fmaf(dA1, h1, v.y * bc.z);
            float p = fmaf(h0, bc.y, h1 * bc.w);
            p += __shfl_xor_sync(0xffffffffu, p, 1);
            p += __shfl_xor_sync(0xffffffffu, p, 2);
            p += __shfl_xor_sync(0xffffffffu, p, 4);
            if (li == 0)
                yp[(size_t)(tb + j) * 512] = (p + v.w) * v.z;
        }
    }
}

// ------------------------- LayerNorm stats + apply ------------------------
__global__ void stats_kernel()
{
    int b = threadIdx.x;
    if (b >= BATCH) return;
    double s = 0.0, ss = 0.0;
    for (int bm = b * 16; bm < b * 16 + 16; ++bm)
        for (int bn = 0; bn < 2; ++bn) {
            int pid = bm * 2 + bn;
            s  += (double)g_psum[2 * pid];
            ss += (double)g_psum[2 * pid + 1];
        }
    const double nd = (double)LSEQ * NOUT;
    double mu = s / nd;
    double var = ss / nd - mu * mu;
    g_stats[b] = make_float2((float)mu, (float)rsqrt(var + 1e-5));
}

__global__ void __launch_bounds__(256)
norm_kernel(float* __restrict__ out, const float* __restrict__ lnw,
            const float* __restrict__ lnb)
{
    size_t i4 = (size_t)blockIdx.x * 256 + threadIdx.x;
    size_t base = i4 * 4;
    int row = (int)(base >> 8);
    int b = row >> 11;
    int l = row & 2047;
    int o = (int)(base & 255);
    float2 st = g_stats[b];
    float4 v = *(float4*)(out + base);
    const float4 w  = *(const float4*)(lnw + (size_t)l * 256 + o);
    const float4 bb = *(const float4*)(lnb + (size_t)l * 256 + o);
    v.x = (v.x - st.x) * st.y * w.x + bb.x;
    v.y = (v.y - st.x) * st.y * w.y + bb.y;
    v.z = (v.z - st.x) * st.y * w.z + bb.z;
    v.w = (v.w - st.x) * st.y * w.w + bb.w;
    *(float4*)(out + base) = v;
}

// ------------------------------- launch -----------------------------------
extern "C" void kernel_launch(void* const* d_in, const int* in_sizes, int n_in,
                              void* d_out, int out_size)
{
    const float* inputs    = (const float*)d_in[0];
    const float* in_proj_w = (const float*)d_in[1];
    const float* conv_w    = (const float*)d_in[2];
    const float* conv_b    = (const float*)d_in[3];
    const float* x_proj_w  = (const float*)d_in[4];
    const float* dt_proj_w = (const float*)d_in[5];
    const float* dt_proj_b = (const float*)d_in[6];
    const float* A_log     = (const float*)d_in[7];
    const float* D_skip    = (const float*)d_in[8];
    const float* out_proj_w= (const float*)d_in[9];
    const float* dim_w     = (const float*)d_in[10];
    const float* dim_b     = (const float*)d_in[11];
    const float* ln_w      = (const float*)d_in[12];
    const float* ln_b      = (const float*)d_in[13];
    float* out = (float*)d_out;

    float *xz, *y, *t1;
    cudaGetSymbolAddress((void**)&xz, g_xz);
    cudaGetSymbolAddress((void**)&y,  g_y);
    cudaGetSymbolAddress((void**)&t1, g_t1);

    // 1) xz = inputs @ in_proj_w^T  [32768 x 1024], silu on z half (bn>=4)
    gemm_bf16_kernel<3><<<dim3(1024 / 128, NROWS / 128), 256>>>(
        inputs, in_proj_w, xz, 1024, 256, nullptr);

    // 2) conv + silu + x_proj + dt_proj, packed scan inputs
    convproj_kernel<<<NROWS / TOK, 512>>>(conv_w, conv_b, x_proj_w,
                                          dt_proj_w, dt_proj_b, D_skip);

    // 3) selective scan
    scan_kernel<<<512, 128>>>(A_log);

    // 4) t1 = silu(y @ out_proj_w^T)  [32768 x 256]
    gemm_bf16_kernel<1><<<dim3(256 / 128, NROWS / 128), 256>>>(
        y, out_proj_w, t1, 256, 512, nullptr);

    // 5) out = t1 @ dim_w^T + dim_b, + per-block partial sums
    gemm_bf16_kernel<2><<<dim3(256 / 128, NROWS / 128), 256>>>(
        t1, dim_w, out, 256, 256, dim_b);

    // 6) per-batch LayerNorm
    stats_kernel<<<1, 32>>>();
    norm_kernel<<<(NROWS * NOUT / 4) / 256, 256>>>(out, ln_w, ln_b);
}